// round 2
// baseline (speedup 1.0000x reference)
#include <cuda_runtime.h>
#include <cstdint>

// ComparatorNBit: A,B float32 [N,32] in {0,1}, MSB first.
// Exact Boolean algebra => pack to 32-bit words, integer compare.
//   d_out[0..N)  = a_gt_b,  d_out[N..2N) = a_eq_b
//
// 8 lanes per row, 2 rows per lane-group (rows g and g+half, both coalesced).
// Bit extraction straight from the float encoding (1.0f has bit 23 set).
// 8-lane OR via REDUX (__reduce_or_sync) instead of shuffle butterfly.

__device__ __forceinline__ unsigned nib_from(const uint4& u) {
    // element x is most significant within the nibble
    return ((u.x >> 20) & 8u) | ((u.y >> 21) & 4u) |
           ((u.z >> 22) & 2u) | ((u.w >> 23) & 1u);
}

__global__ void __launch_bounds__(256) comparator_nbit_kernel(
    const uint4* __restrict__ A4,
    const uint4* __restrict__ B4,
    float* __restrict__ out,
    int n, int half)
{
    int gid = blockIdx.x * blockDim.x + threadIdx.x;
    int g   = gid >> 3;        // lane-group id = first row index
    int sub = gid & 7;         // which 16B chunk within the row
    if (g >= half) return;

    int r0 = g;
    int r1 = g + half;
    bool has2 = (r1 < n);

    // Front-batched independent loads (MLP=4), streaming policy.
    uint4 a0 = __ldcs(A4 + (size_t)r0 * 8 + sub);
    uint4 b0 = __ldcs(B4 + (size_t)r0 * 8 + sub);
    uint4 a1 = make_uint4(0u, 0u, 0u, 0u);
    uint4 b1 = make_uint4(0u, 0u, 0u, 0u);
    if (has2) {
        a1 = __ldcs(A4 + (size_t)r1 * 8 + sub);
        b1 = __ldcs(B4 + (size_t)r1 * 8 + sub);
    }

    unsigned sh = 28u - 4u * (unsigned)sub;   // nibble position in the word
    unsigned pa0 = nib_from(a0) << sh;
    unsigned pb0 = nib_from(b0) << sh;
    unsigned pa1 = nib_from(a1) << sh;
    unsigned pb1 = nib_from(b1) << sh;

    // OR across the 8-lane group in one REDUX each.
    unsigned mask = 0xFFu << (threadIdx.x & 24);
    pa0 = __reduce_or_sync(mask, pa0);
    pb0 = __reduce_or_sync(mask, pb0);
    pa1 = __reduce_or_sync(mask, pa1);
    pb1 = __reduce_or_sync(mask, pb1);

    if (sub == 0) {
        out[r0]     = (pa0 >  pb0) ? 1.0f : 0.0f;
        out[n + r0] = (pa0 == pb0) ? 1.0f : 0.0f;
        if (has2) {
            out[r1]     = (pa1 >  pb1) ? 1.0f : 0.0f;
            out[n + r1] = (pa1 == pb1) ? 1.0f : 0.0f;
        }
    }
}

extern "C" void kernel_launch(void* const* d_in, const int* in_sizes, int n_in,
                              void* d_out, int out_size)
{
    const uint4* A4 = (const uint4*)d_in[0];
    const uint4* B4 = (const uint4*)d_in[1];
    float* out = (float*)d_out;

    int n = in_sizes[0] / 32;          // rows
    int half = (n + 1) / 2;            // rows per pass; group g does g and g+half
    long long total_threads = (long long)half * 8;
    int block = 256;
    int grid = (int)((total_threads + block - 1) / block);

    comparator_nbit_kernel<<<grid, block>>>(A4, B4, out, n, half);
}

// round 3
// speedup vs baseline: 1.0421x; 1.0421x over previous
#include <cuda_runtime.h>
#include <cstdint>

// ComparatorNBit: A,B float32 [N,32] in {0,1}, MSB first.
// Exact Boolean algebra => pack to 32-bit words, unsigned integer compare.
//   d_out[0..N)  = a_gt_b,  d_out[N..2N) = a_eq_b
//
// 8 lanes per row, each 8-lane group handles TWO ADJACENT rows (2g, 2g+1):
// 4 front-batched LDG.128 per thread (MLP=4) all within a 256B span; each
// warp reads one contiguous 1KB segment per array. Bits come straight from
// the float encoding (1.0f = 0x3F800000, bit 23). 8-lane OR via REDUX.

__device__ __forceinline__ unsigned nib_from(const uint4& u) {
    // element .x is most significant within the nibble
    return ((u.x >> 20) & 8u) | ((u.y >> 21) & 4u) |
           ((u.z >> 22) & 2u) | ((u.w >> 23) & 1u);
}

__global__ void __launch_bounds__(256) comparator_nbit_kernel(
    const uint4* __restrict__ A4,
    const uint4* __restrict__ B4,
    float* __restrict__ out,
    int n)
{
    int gid = blockIdx.x * blockDim.x + threadIdx.x;
    int g   = gid >> 3;        // group id; handles rows 2g and 2g+1
    int sub = gid & 7;         // 16B chunk within a row

    int r0 = 2 * g;
    int r1 = 2 * g + 1;
    if (r0 >= n) return;

    // Front-batched loads, all within a 256B window per thread.
    size_t base0 = (size_t)r0 * 8 + sub;
    uint4 a0 = A4[base0];
    uint4 b0 = B4[base0];
    uint4 a1, b1;
    if (r1 < n) {
        a1 = A4[base0 + 8];
        b1 = B4[base0 + 8];
    } else {
        a1 = make_uint4(0u, 0u, 0u, 0u);
        b1 = make_uint4(0u, 0u, 0u, 0u);
    }

    unsigned sh = 28u - 4u * (unsigned)sub;
    unsigned pa0 = nib_from(a0) << sh;
    unsigned pb0 = nib_from(b0) << sh;
    unsigned pa1 = nib_from(a1) << sh;
    unsigned pb1 = nib_from(b1) << sh;

    // OR across each 8-lane group with a single REDUX per word.
    unsigned mask = 0xFFu << (threadIdx.x & 24);
    pa0 = __reduce_or_sync(mask, pa0);
    pb0 = __reduce_or_sync(mask, pb0);
    pa1 = __reduce_or_sync(mask, pa1);
    pb1 = __reduce_or_sync(mask, pb1);

    if (sub == 0) {
        out[r0]     = (pa0 >  pb0) ? 1.0f : 0.0f;
        out[n + r0] = (pa0 == pb0) ? 1.0f : 0.0f;
        if (r1 < n) {
            out[r1]     = (pa1 >  pb1) ? 1.0f : 0.0f;
            out[n + r1] = (pa1 == pb1) ? 1.0f : 0.0f;
        }
    }
}

extern "C" void kernel_launch(void* const* d_in, const int* in_sizes, int n_in,
                              void* d_out, int out_size)
{
    const uint4* A4 = (const uint4*)d_in[0];
    const uint4* B4 = (const uint4*)d_in[1];
    float* out = (float*)d_out;

    int n = in_sizes[0] / 32;                  // rows
    int groups = (n + 1) / 2;                  // 2 rows per group
    long long total_threads = (long long)groups * 8;
    int block = 256;
    int grid = (int)((total_threads + block - 1) / block);

    comparator_nbit_kernel<<<grid, block>>>(A4, B4, out, n);
}

// round 4
// speedup vs baseline: 1.0691x; 1.0258x over previous
#include <cuda_runtime.h>
#include <cstdint>

// ComparatorNBit: A,B float32 [N,32] in {0,1}, MSB first.
// Exact Boolean algebra => 32-bit unsigned compare of the packed words.
//   d_out[0..N) = a_gt_b,  d_out[N..2N) = a_eq_b
//
// 8 lanes per row chunk; each 8-lane group handles FOUR adjacent rows
// (4g..4g+3): 8 front-batched LDG.128 per thread (MLP=8) within a 512B
// span. Per-lane nibble value built with 3 FFMA (values are exact {0,1}
// floats), compared with FSETP; cross-lane priority via ballot + lsb
// isolate (lowest sub = most significant nibble). Lane 0 stores float4.

__device__ __forceinline__ float nibf(const float4& v) {
    // exact: nibble value 0..15 as float (fma pipe, not alu)
    return fmaf(v.x, 8.0f, fmaf(v.y, 4.0f, fmaf(v.z, 2.0f, v.w)));
}

__global__ void __launch_bounds__(256) comparator_nbit_kernel(
    const float4* __restrict__ A4,
    const float4* __restrict__ B4,
    float* __restrict__ out,
    int n)
{
    int gid = blockIdx.x * blockDim.x + threadIdx.x;
    int g   = gid >> 3;        // group: rows 4g .. 4g+3
    int sub = gid & 7;         // 16B chunk within a row (0 = MSBs)
    int r0  = g << 2;

    float4 a[4], b[4];
    if (r0 + 3 < n) {
        size_t base = (size_t)r0 * 8 + sub;
        #pragma unroll
        for (int i = 0; i < 4; i++) {
            a[i] = A4[base + 8 * i];
            b[i] = B4[base + 8 * i];
        }
    } else {
        #pragma unroll
        for (int i = 0; i < 4; i++) {       // tail: clamp, results discarded
            int r = min(r0 + i, n - 1);
            size_t idx = (size_t)r * 8 + sub;
            a[i] = A4[idx];
            b[i] = B4[idx];
        }
    }

    unsigned bal_ne[4], bal_gt[4];
    #pragma unroll
    for (int i = 0; i < 4; i++) {
        float fa = nibf(a[i]);
        float fb = nibf(b[i]);
        bal_ne[i] = __ballot_sync(0xffffffffu, fa != fb);
        bal_gt[i] = __ballot_sync(0xffffffffu, fa >  fb);
    }

    if (sub == 0) {
        unsigned shift = threadIdx.x & 24u;   // group's byte within the ballot
        float gtv[4], eqv[4];
        #pragma unroll
        for (int i = 0; i < 4; i++) {
            unsigned ne8 = (bal_ne[i] >> shift) & 0xFFu;
            unsigned lsb = ne8 & (0u - ne8);  // first differing nibble (MSB-first)
            gtv[i] = ((bal_gt[i] >> shift) & lsb) ? 1.0f : 0.0f;
            eqv[i] = (ne8 == 0u) ? 1.0f : 0.0f;
        }
        if ((r0 + 3 < n) && ((n & 3) == 0)) {
            *(float4*)(out + r0)     = make_float4(gtv[0], gtv[1], gtv[2], gtv[3]);
            *(float4*)(out + n + r0) = make_float4(eqv[0], eqv[1], eqv[2], eqv[3]);
        } else {
            #pragma unroll
            for (int i = 0; i < 4; i++)
                if (r0 + i < n) {
                    out[r0 + i]     = gtv[i];
                    out[n + r0 + i] = eqv[i];
                }
        }
    }
}

extern "C" void kernel_launch(void* const* d_in, const int* in_sizes, int n_in,
                              void* d_out, int out_size)
{
    const float4* A4 = (const float4*)d_in[0];
    const float4* B4 = (const float4*)d_in[1];
    float* out = (float*)d_out;

    int n = in_sizes[0] / 32;                    // rows
    long long groups = (n + 3) / 4;              // 4 rows per group
    long long total_threads = groups * 8;
    int block = 256;
    int grid = (int)((total_threads + block - 1) / block);

    comparator_nbit_kernel<<<grid, block>>>(A4, B4, out, n);
}

// round 5
// speedup vs baseline: 1.0743x; 1.0049x over previous
#include <cuda_runtime.h>
#include <cstdint>

// ComparatorNBit: A,B float32 [N,32] in {0,1}, MSB first.
// Exact Boolean algebra => 32-bit unsigned compare of packed words.
//   d_out[0..N) = a_gt_b,  d_out[N..2N) = a_eq_b
//
// 8 lanes per row chunk; each 8-lane group handles EIGHT adjacent rows
// (8g..8g+7): 16 front-batched LDG.128 per thread (MLP=16) within a 1KB
// span; each warp reads contiguous 4KB per array. Per-lane nibble value
// built with 3 FFMA (values are exact {0,1} floats); cross-lane priority
// via ballot + lsb isolate (lowest sub = most significant nibble).
// Lane 0 stores 2x float4 per output array.

#define ROWS_PER_GROUP 8

__device__ __forceinline__ float nibf(const float4& v) {
    // exact: nibble value 0..15 as float (fma pipe)
    return fmaf(v.x, 8.0f, fmaf(v.y, 4.0f, fmaf(v.z, 2.0f, v.w)));
}

__global__ void __launch_bounds__(256) comparator_nbit_kernel(
    const float4* __restrict__ A4,
    const float4* __restrict__ B4,
    float* __restrict__ out,
    int n)
{
    int gid = blockIdx.x * blockDim.x + threadIdx.x;
    int g   = gid >> 3;                 // group: rows 8g .. 8g+7
    int sub = gid & 7;                  // 16B chunk within a row (0 = MSBs)
    int r0  = g << 3;
    if (r0 >= n) return;

    float4 a[ROWS_PER_GROUP], b[ROWS_PER_GROUP];
    if (r0 + ROWS_PER_GROUP - 1 < n) {
        size_t base = (size_t)r0 * 8 + sub;
        #pragma unroll
        for (int i = 0; i < ROWS_PER_GROUP; i++) {
            a[i] = A4[base + 8 * i];
            b[i] = B4[base + 8 * i];
        }
    } else {
        #pragma unroll
        for (int i = 0; i < ROWS_PER_GROUP; i++) {   // tail: clamp, extras discarded
            int r = min(r0 + i, n - 1);
            size_t idx = (size_t)r * 8 + sub;
            a[i] = A4[idx];
            b[i] = B4[idx];
        }
    }

    unsigned bal_ne[ROWS_PER_GROUP], bal_gt[ROWS_PER_GROUP];
    #pragma unroll
    for (int i = 0; i < ROWS_PER_GROUP; i++) {
        float fa = nibf(a[i]);
        float fb = nibf(b[i]);
        bal_ne[i] = __ballot_sync(0xffffffffu, fa != fb);
        bal_gt[i] = __ballot_sync(0xffffffffu, fa >  fb);
    }

    if (sub == 0) {
        unsigned shift = threadIdx.x & 24u;   // this group's byte of the ballot
        float gtv[ROWS_PER_GROUP], eqv[ROWS_PER_GROUP];
        #pragma unroll
        for (int i = 0; i < ROWS_PER_GROUP; i++) {
            unsigned ne8 = (bal_ne[i] >> shift) & 0xFFu;
            unsigned lsb = ne8 & (0u - ne8);  // first differing nibble (MSB-first)
            gtv[i] = ((bal_gt[i] >> shift) & lsb) ? 1.0f : 0.0f;
            eqv[i] = (ne8 == 0u) ? 1.0f : 0.0f;
        }
        if ((r0 + ROWS_PER_GROUP - 1 < n) && ((n & 7) == 0)) {
            *(float4*)(out + r0)         = make_float4(gtv[0], gtv[1], gtv[2], gtv[3]);
            *(float4*)(out + r0 + 4)     = make_float4(gtv[4], gtv[5], gtv[6], gtv[7]);
            *(float4*)(out + n + r0)     = make_float4(eqv[0], eqv[1], eqv[2], eqv[3]);
            *(float4*)(out + n + r0 + 4) = make_float4(eqv[4], eqv[5], eqv[6], eqv[7]);
        } else {
            #pragma unroll
            for (int i = 0; i < ROWS_PER_GROUP; i++)
                if (r0 + i < n) {
                    out[r0 + i]     = gtv[i];
                    out[n + r0 + i] = eqv[i];
                }
        }
    }
}

extern "C" void kernel_launch(void* const* d_in, const int* in_sizes, int n_in,
                              void* d_out, int out_size)
{
    const float4* A4 = (const float4*)d_in[0];
    const float4* B4 = (const float4*)d_in[1];
    float* out = (float*)d_out;

    int n = in_sizes[0] / 32;                            // rows
    long long groups = (n + ROWS_PER_GROUP - 1) / ROWS_PER_GROUP;
    long long total_threads = groups * 8;
    int block = 256;
    int grid = (int)((total_threads + block - 1) / block);

    comparator_nbit_kernel<<<grid, block>>>(A4, B4, out, n);
}